// round 3
// baseline (speedup 1.0000x reference)
#include <cuda_runtime.h>

#define SEQ    2048
#define DIM    256
#define NHEAD  8
#define NBATCH 8
#define NROWS  (NBATCH*SEQ)     // 16384
#define HBTOT  (NHEAD*NBATCH)   // 64

// scratch: q,k,v,o  each [H*B][S][D] fp32 = 128 MB
__device__ float g_q[(size_t)HBTOT*SEQ*DIM];
__device__ float g_k[(size_t)HBTOT*SEQ*DIM];
__device__ float g_v[(size_t)HBTOT*SEQ*DIM];
__device__ float g_o[(size_t)HBTOT*SEQ*DIM];

// ---------------------------------------------------------------------------
// Kernel 1: QKV projections.  out[h,r,d] = sum_f A[r,f]*W[h,f,d] + b[h,d]
// grid: (4 n-tiles, 256 m-tiles, 24 matrices), block 16x16, 64x64x16 tiling.
// ---------------------------------------------------------------------------
__global__ __launch_bounds__(256) void proj_kernel(
    const float* __restrict__ x, const float* __restrict__ lstm,
    const float* __restrict__ Qw, const float* __restrict__ Qb,
    const float* __restrict__ Kw, const float* __restrict__ Kb,
    const float* __restrict__ Vw, const float* __restrict__ Vb)
{
    __shared__ float As[16][64];
    __shared__ float Bs[16][64];

    const int bz = blockIdx.z;
    const int type = bz >> 3, h = bz & 7;
    const float* A; const float* W; const float* bias; float* out;
    if (type == 0)      { A = lstm; W = Qw; bias = Qb; out = g_q; }
    else if (type == 1) { A = x;    W = Kw; bias = Kb; out = g_k; }
    else                { A = x;    W = Vw; bias = Vb; out = g_v; }
    W    += h * DIM * DIM;
    bias += h * DIM;
    out  += (size_t)h * NROWS * DIM;

    const int r0 = blockIdx.y * 64, d0 = blockIdx.x * 64;
    const int tx = threadIdx.x, ty = threadIdx.y;
    const int tid = ty * 16 + tx;

    const int arow = tid >> 2,  ak4 = (tid & 3)  * 4;
    const int brow = tid >> 4,  bc4 = (tid & 15) * 4;

    float acc[4][4] = {};

    for (int kt = 0; kt < DIM; kt += 16) {
        float4 a = *(const float4*)&A[(size_t)(r0 + arow) * DIM + kt + ak4];
        float4 b = *(const float4*)&W[(size_t)(kt + brow) * DIM + d0 + bc4];
        __syncthreads();   // previous iteration's compute done
        As[ak4 + 0][arow] = a.x;
        As[ak4 + 1][arow] = a.y;
        As[ak4 + 2][arow] = a.z;
        As[ak4 + 3][arow] = a.w;
        *(float4*)&Bs[brow][bc4] = b;
        __syncthreads();
        #pragma unroll
        for (int kk = 0; kk < 16; kk++) {
            float4 av = *(const float4*)&As[kk][ty * 4];
            float4 bv = *(const float4*)&Bs[kk][tx * 4];
            float am[4] = {av.x, av.y, av.z, av.w};
            float bm[4] = {bv.x, bv.y, bv.z, bv.w};
            #pragma unroll
            for (int i = 0; i < 4; i++)
                #pragma unroll
                for (int j = 0; j < 4; j++)
                    acc[i][j] = fmaf(am[i], bm[j], acc[i][j]);
        }
    }

    #pragma unroll
    for (int i = 0; i < 4; i++) {
        float4 o;
        o.x = acc[i][0] + bias[d0 + tx * 4 + 0];
        o.y = acc[i][1] + bias[d0 + tx * 4 + 1];
        o.z = acc[i][2] + bias[d0 + tx * 4 + 2];
        o.w = acc[i][3] + bias[d0 + tx * 4 + 3];
        *(float4*)&out[(size_t)(r0 + ty * 4 + i) * DIM + d0 + tx * 4] = o;
    }
}

// ---------------------------------------------------------------------------
// Kernel 2: flash attention, fp32.  grid (32 q-tiles, 64 hb), 256 threads.
// Warp w owns q rows w*8..w*8+7; lane c is a score column (32-wide K tiles).
// PV tile skipped (exactly-zero contribution) when tile max < running max-35.
// ---------------------------------------------------------------------------
#define FLASH_SMEM ((64*256 + 32*260 + 32*256 + 64*33) * 4)

__global__ __launch_bounds__(256, 1) void flash_kernel()
{
    extern __shared__ float sm[];
    float* Qs = sm;               // [64][256]
    float* Ks = sm + 64 * 256;    // [32][260]  (padded rows: conflict reduction)
    float* Vs = Ks + 32 * 260;    // [32][256]
    float* Ps = Vs + 32 * 256;    // [64][33]

    const int qt = blockIdx.x;    // 0..31
    const int hb = blockIdx.y;    // 0..63
    const size_t base = (size_t)hb * SEQ * DIM;
    const int tid = threadIdx.x;
    const int w = tid >> 5, c = tid & 31;

    // load Q tile 64x256
    #pragma unroll
    for (int i = 0; i < 16; i++) {
        int u = tid + i * 256;            // 0..4095
        int row = u >> 6, k4 = (u & 63) * 4;
        *(float4*)&Qs[row * 256 + k4] =
            *(const float4*)&g_q[base + (size_t)(qt * 64 + row) * DIM + k4];
    }

    float o[8][8];
    #pragma unroll
    for (int i = 0; i < 8; i++)
        #pragma unroll
        for (int j = 0; j < 8; j++) o[i][j] = 0.f;
    float m[8], l[8];
    #pragma unroll
    for (int i = 0; i < 8; i++) { m[i] = -3.0e38f; l[i] = 0.f; }

    for (int kt = 0; kt < SEQ / 32; kt++) {
        __syncthreads();  // everyone done reading previous K/V
        #pragma unroll
        for (int i = 0; i < 8; i++) {
            int u = tid + i * 256;        // 0..2047
            int j = u >> 6, k4 = (u & 63) * 4;
            *(float4*)&Ks[j * 260 + k4] =
                *(const float4*)&g_k[base + (size_t)(kt * 32 + j) * DIM + k4];
            *(float4*)&Vs[j * 256 + k4] =
                *(const float4*)&g_v[base + (size_t)(kt * 32 + j) * DIM + k4];
        }
        __syncthreads();

        // scores: s[rr] = q_row(rr) . k_col(c), 4 partial chains for accuracy
        float sA[8] = {}, sB[8] = {}, sC[8] = {}, sD[8] = {};
        const float* krow = &Ks[c * 260];
        #pragma unroll 4
        for (int k4 = 0; k4 < 64; k4++) {
            float4 kv = *(const float4*)&krow[k4 * 4];
            #pragma unroll
            for (int rr = 0; rr < 8; rr++) {
                float4 qv = *(const float4*)&Qs[(w * 8 + rr) * 256 + k4 * 4];
                sA[rr] = fmaf(qv.x, kv.x, sA[rr]);
                sB[rr] = fmaf(qv.y, kv.y, sB[rr]);
                sC[rr] = fmaf(qv.z, kv.z, sC[rr]);
                sD[rr] = fmaf(qv.w, kv.w, sD[rr]);
            }
        }

        // combine, tile max, activity test (warp-uniform)
        bool active = false;
        #pragma unroll
        for (int rr = 0; rr < 8; rr++) {
            float sv = ((sA[rr] + sB[rr]) + (sC[rr] + sD[rr])) * 0.0625f;
            sA[rr] = sv;                  // reuse as score
            float tm = sv;
            #pragma unroll
            for (int off = 16; off > 0; off >>= 1)
                tm = fmaxf(tm, __shfl_xor_sync(0xffffffffu, tm, off));
            sB[rr] = tm;                  // reuse as tile max
            if (tm >= m[rr] - 35.0f) active = true;
        }

        if (active) {
            #pragma unroll
            for (int rr = 0; rr < 8; rr++) {
                float nm  = fmaxf(m[rr], sB[rr]);
                float fac = __expf(m[rr] - nm);
                float p   = __expf(sA[rr] - nm);
                float ps  = p;
                #pragma unroll
                for (int off = 16; off > 0; off >>= 1)
                    ps += __shfl_xor_sync(0xffffffffu, ps, off);
                l[rr] = l[rr] * fac + ps;
                m[rr] = nm;
                Ps[(w * 8 + rr) * 33 + c] = p;
                #pragma unroll
                for (int j = 0; j < 8; j++) o[rr][j] *= fac;
            }
            __syncwarp();

            // PV: o[rr][c*8..c*8+7] += sum_j P[rr][j] * V[j][...]
            for (int j = 0; j < 32; j++) {
                float4 v0 = *(const float4*)&Vs[j * 256 + c * 8];
                float4 v1 = *(const float4*)&Vs[j * 256 + c * 8 + 4];
                float pv[8];
                #pragma unroll
                for (int rr = 0; rr < 8; rr++) pv[rr] = Ps[(w * 8 + rr) * 33 + j];
                #pragma unroll
                for (int rr = 0; rr < 8; rr++) {
                    o[rr][0] = fmaf(pv[rr], v0.x, o[rr][0]);
                    o[rr][1] = fmaf(pv[rr], v0.y, o[rr][1]);
                    o[rr][2] = fmaf(pv[rr], v0.z, o[rr][2]);
                    o[rr][3] = fmaf(pv[rr], v0.w, o[rr][3]);
                    o[rr][4] = fmaf(pv[rr], v1.x, o[rr][4]);
                    o[rr][5] = fmaf(pv[rr], v1.y, o[rr][5]);
                    o[rr][6] = fmaf(pv[rr], v1.z, o[rr][6]);
                    o[rr][7] = fmaf(pv[rr], v1.w, o[rr][7]);
                }
            }
            __syncwarp();
        }
    }

    // epilogue: normalize and store
    #pragma unroll
    for (int rr = 0; rr < 8; rr++) {
        float inv = 1.0f / l[rr];
        float* dst = &g_o[base + (size_t)(qt * 64 + w * 8 + rr) * DIM + c * 8];
        float4 a = make_float4(o[rr][0] * inv, o[rr][1] * inv, o[rr][2] * inv, o[rr][3] * inv);
        float4 b = make_float4(o[rr][4] * inv, o[rr][5] * inv, o[rr][6] * inv, o[rr][7] * inv);
        *(float4*)&dst[0] = a;
        *(float4*)&dst[4] = b;
    }
}

// ---------------------------------------------------------------------------
// Kernel 3: out[r,n] = sum_{h,d} o[h,r,d] * Cw[h*256+d, n] + Cb[n]
// block = 8 rows (warp per row), Cw staged in smem (64 KB).
// ---------------------------------------------------------------------------
__global__ __launch_bounds__(256) void final_kernel(
    const float* __restrict__ Cw, const float* __restrict__ Cb,
    float* __restrict__ out)
{
    extern __shared__ float cws[];   // 2048*8 floats
    const int tid = threadIdx.x;
    for (int i = tid; i < 4096; i += 256)
        ((float4*)cws)[i] = ((const float4*)Cw)[i];
    __syncthreads();

    const int w = tid >> 5, c = tid & 31;
    const int r = blockIdx.x * 8 + w;

    float acc[8] = {};
    #pragma unroll
    for (int h = 0; h < NHEAD; h++) {
        const float* orow = &g_o[((size_t)h * NROWS + r) * DIM];
        #pragma unroll
        for (int i = 0; i < 8; i++) {
            int d = c + i * 32;
            float ov = orow[d];
            const float* cwr = &cws[(h * DIM + d) * 8];
            #pragma unroll
            for (int n = 0; n < 8; n++)
                acc[n] = fmaf(ov, cwr[n], acc[n]);
        }
    }
    #pragma unroll
    for (int n = 0; n < 8; n++) {
        #pragma unroll
        for (int off = 16; off > 0; off >>= 1)
            acc[n] += __shfl_xor_sync(0xffffffffu, acc[n], off);
    }
    if (c == 0) {
        #pragma unroll
        for (int n = 0; n < 8; n++)
            out[r * 8 + n] = acc[n] + Cb[n];
    }
}

// ---------------------------------------------------------------------------
extern "C" void kernel_launch(void* const* d_in, const int* in_sizes, int n_in,
                              void* d_out, int out_size)
{
    const float* x    = (const float*)d_in[0];
    const float* lstm = (const float*)d_in[1];
    const float* Qw   = (const float*)d_in[2];
    const float* Qb   = (const float*)d_in[3];
    const float* Kw   = (const float*)d_in[4];
    const float* Kb   = (const float*)d_in[5];
    const float* Vw   = (const float*)d_in[6];
    const float* Vb   = (const float*)d_in[7];
    const float* Cw   = (const float*)d_in[8];
    const float* Cb   = (const float*)d_in[9];
    float* out = (float*)d_out;

    cudaFuncSetAttribute(flash_kernel, cudaFuncAttributeMaxDynamicSharedMemorySize, FLASH_SMEM);
    cudaFuncSetAttribute(final_kernel, cudaFuncAttributeMaxDynamicSharedMemorySize, 65536);

    proj_kernel<<<dim3(4, 256, 24), dim3(16, 16)>>>(x, lstm, Qw, Qb, Kw, Kb, Vw, Vb);
    flash_kernel<<<dim3(32, 64), 256, FLASH_SMEM>>>();
    final_kernel<<<2048, 256, 65536>>>(Cw, Cb, out);
}

// round 5
// speedup vs baseline: 1.1996x; 1.1996x over previous
#include <cuda_runtime.h>

#define SEQ    2048
#define DIM    256
#define NHEAD  8
#define NBATCH 8
#define NROWS  (NBATCH*SEQ)     // 16384
#define HBTOT  (NHEAD*NBATCH)   // 64

typedef unsigned long long ull;

// scratch: q,k,v,o  each [H*B][S][D] fp32 = 128 MB
__device__ float g_q[(size_t)HBTOT*SEQ*DIM];
__device__ float g_k[(size_t)HBTOT*SEQ*DIM];
__device__ float g_v[(size_t)HBTOT*SEQ*DIM];
__device__ float g_o[(size_t)HBTOT*SEQ*DIM];

// ---------------------------------------------------------------------------
// packed f32x2 helpers (FFMA2 path: only reachable via PTX fma.rn.f32x2)
// ---------------------------------------------------------------------------
__device__ __forceinline__ ull pk2(float lo, float hi) {
    ull r; asm("mov.b64 %0, {%1,%2};" : "=l"(r) : "f"(lo), "f"(hi)); return r;
}
__device__ __forceinline__ void upk2(ull v, float& lo, float& hi) {
    asm("mov.b64 {%0,%1}, %2;" : "=f"(lo), "=f"(hi) : "l"(v));
}
__device__ __forceinline__ ull ffma2(ull a, ull b, ull c) {
    ull d; asm("fma.rn.f32x2 %0, %1, %2, %3;" : "=l"(d) : "l"(a), "l"(b), "l"(c));
    return d;
}
__device__ __forceinline__ ull fmul2(ull a, ull b) {
    ull d; asm("mul.rn.f32x2 %0, %1, %2;" : "=l"(d) : "l"(a), "l"(b));
    return d;
}

// ---------------------------------------------------------------------------
// Kernel 1: QKV projections.  out[h,r,d] = sum_f A[r,f]*W[h,f,d] + b[h,d]
// grid: (4 n-tiles, 256 m-tiles, 24 matrices), block 16x16, 64x64x16 tiling.
// Inner product uses FFMA2 (b-pairs pre-packed from shared, a dup'd via MOV).
// ---------------------------------------------------------------------------
__global__ __launch_bounds__(256) void proj_kernel(
    const float* __restrict__ x, const float* __restrict__ lstm,
    const float* __restrict__ Qw, const float* __restrict__ Qb,
    const float* __restrict__ Kw, const float* __restrict__ Kb,
    const float* __restrict__ Vw, const float* __restrict__ Vb)
{
    __shared__ float As[16][64];
    __shared__ float Bs[16][64];

    const int bz = blockIdx.z;
    const int type = bz >> 3, h = bz & 7;
    const float* A; const float* W; const float* bias; float* out;
    if (type == 0)      { A = lstm; W = Qw; bias = Qb; out = g_q; }
    else if (type == 1) { A = x;    W = Kw; bias = Kb; out = g_k; }
    else                { A = x;    W = Vw; bias = Vb; out = g_v; }
    W    += h * DIM * DIM;
    bias += h * DIM;
    out  += (size_t)h * NROWS * DIM;

    const int r0 = blockIdx.y * 64, d0 = blockIdx.x * 64;
    const int tx = threadIdx.x, ty = threadIdx.y;
    const int tid = ty * 16 + tx;

    const int arow = tid >> 2,  ak4 = (tid & 3)  * 4;
    const int brow = tid >> 4,  bc4 = (tid & 15) * 4;

    ull acc[4][2];
    #pragma unroll
    for (int i = 0; i < 4; i++) { acc[i][0] = 0ull; acc[i][1] = 0ull; }

    for (int kt = 0; kt < DIM; kt += 16) {
        float4 a = *(const float4*)&A[(size_t)(r0 + arow) * DIM + kt + ak4];
        float4 b = *(const float4*)&W[(size_t)(kt + brow) * DIM + d0 + bc4];
        __syncthreads();   // previous iteration's compute done
        As[ak4 + 0][arow] = a.x;
        As[ak4 + 1][arow] = a.y;
        As[ak4 + 2][arow] = a.z;
        As[ak4 + 3][arow] = a.w;
        *(float4*)&Bs[brow][bc4] = b;
        __syncthreads();
        #pragma unroll
        for (int kk = 0; kk < 16; kk++) {
            float4 av = *(const float4*)&As[kk][ty * 4];
            ulonglong2 bv = *(const ulonglong2*)&Bs[kk][tx * 4];
            ull a0 = pk2(av.x, av.x), a1 = pk2(av.y, av.y);
            ull a2 = pk2(av.z, av.z), a3 = pk2(av.w, av.w);
            acc[0][0] = ffma2(a0, bv.x, acc[0][0]);
            acc[0][1] = ffma2(a0, bv.y, acc[0][1]);
            acc[1][0] = ffma2(a1, bv.x, acc[1][0]);
            acc[1][1] = ffma2(a1, bv.y, acc[1][1]);
            acc[2][0] = ffma2(a2, bv.x, acc[2][0]);
            acc[2][1] = ffma2(a2, bv.y, acc[2][1]);
            acc[3][0] = ffma2(a3, bv.x, acc[3][0]);
            acc[3][1] = ffma2(a3, bv.y, acc[3][1]);
        }
    }

    #pragma unroll
    for (int i = 0; i < 4; i++) {
        float4 o;
        upk2(acc[i][0], o.x, o.y);
        upk2(acc[i][1], o.z, o.w);
        o.x += bias[d0 + tx * 4 + 0];
        o.y += bias[d0 + tx * 4 + 1];
        o.z += bias[d0 + tx * 4 + 2];
        o.w += bias[d0 + tx * 4 + 3];
        *(float4*)&out[(size_t)(r0 + ty * 4 + i) * DIM + d0 + tx * 4] = o;
    }
}

// ---------------------------------------------------------------------------
// Kernel 2: flash attention, fp32 with FFMA2.  grid (32 q-tiles, 64 hb), 256 thr.
// Warp w owns q rows w*8..w*8+7; lane c owns score columns c and c+32 of a
// 64-wide K tile (q broadcast amortized over 2 columns).
// K smem: float4 column XOR-swizzled by (row&7)  -> conflict-free per-lane loads.
// V smem: even/odd float4 interleave -> lane-c reads dims 8c..8c+7 conflict-free.
// PV tile skipped (exactly-zero contribution) when tile max < running max-35.
// ---------------------------------------------------------------------------
#define FLASH_SMEM ((3*64*256 + 64*64) * 4)   // 212992 bytes

__global__ __launch_bounds__(256, 1) void flash_kernel()
{
    extern __shared__ float sm[];
    float* Qs = sm;               // [64][256] linear
    float* Ks = sm + 64 * 256;    // [64][256] xor-swizzled float4 columns
    float* Vs = Ks + 64 * 256;    // [64][256] even/odd interleaved float4s
    float* Ps = Vs + 64 * 256;    // [64][64]

    const int qt = blockIdx.x;    // 0..31
    const int hb = blockIdx.y;    // 0..63
    const size_t base = (size_t)hb * SEQ * DIM;
    const int tid = threadIdx.x;
    const int w = tid >> 5, c = tid & 31;

    // load Q tile 64x256
    #pragma unroll
    for (int i = 0; i < 16; i++) {
        int u = tid + i * 256;            // 0..4095
        int row = u >> 6, k4 = u & 63;
        *(float4*)&Qs[row * 256 + k4 * 4] =
            *(const float4*)&g_q[base + (size_t)(qt * 64 + row) * DIM + k4 * 4];
    }

    ull o[8][4];                  // packed pairs covering dims 8c..8c+7
    #pragma unroll
    for (int i = 0; i < 8; i++)
        #pragma unroll
        for (int j = 0; j < 4; j++) o[i][j] = 0ull;
    float m[8], l[8];
    #pragma unroll
    for (int i = 0; i < 8; i++) { m[i] = -3.0e38f; l[i] = 0.f; }

    const int cx = c & 7;

    for (int kt = 0; kt < SEQ / 64; kt++) {
        __syncthreads();  // everyone done reading previous K/V
        #pragma unroll
        for (int i = 0; i < 16; i++) {
            int u = tid + i * 256;        // 0..4095
            int row = u >> 6, k4 = u & 63;
            *(float4*)&Ks[row * 256 + ((k4 ^ (row & 7)) << 2)] =
                *(const float4*)&g_k[base + (size_t)(kt * 64 + row) * DIM + k4 * 4];
            int pos = (k4 & 1) ? (32 + (k4 >> 1)) : (k4 >> 1);
            *(float4*)&Vs[row * 256 + (pos << 2)] =
                *(const float4*)&g_v[base + (size_t)(kt * 64 + row) * DIM + k4 * 4];
        }
        __syncthreads();

        // QK: lane computes s[rr][col c] and s[rr][col c+32]; packed over dims.
        ull acc[8][2];
        #pragma unroll
        for (int rr = 0; rr < 8; rr++) { acc[rr][0] = 0ull; acc[rr][1] = 0ull; }

        const float* k0p = &Ks[c * 256];
        const float* k1p = &Ks[(c + 32) * 256];   // same xor: (c+32)&7 == c&7
        #pragma unroll 4
        for (int k4 = 0; k4 < 64; k4++) {
            int sc = (k4 ^ cx) << 2;
            ulonglong2 kv0 = *(const ulonglong2*)&k0p[sc];
            ulonglong2 kv1 = *(const ulonglong2*)&k1p[sc];
            #pragma unroll
            for (int rr = 0; rr < 8; rr++) {
                ulonglong2 qv = *(const ulonglong2*)&Qs[(w * 8 + rr) * 256 + k4 * 4];
                acc[rr][0] = ffma2(qv.x, kv0.x, acc[rr][0]);
                acc[rr][0] = ffma2(qv.y, kv0.y, acc[rr][0]);
                acc[rr][1] = ffma2(qv.x, kv1.x, acc[rr][1]);
                acc[rr][1] = ffma2(qv.y, kv1.y, acc[rr][1]);
            }
        }

        // combine, tile max, activity test (warp-uniform)
        float s0[8], s1[8], tmax[8];
        bool active = false;
        #pragma unroll
        for (int rr = 0; rr < 8; rr++) {
            float a, b;
            upk2(acc[rr][0], a, b); s0[rr] = (a + b) * 0.0625f;
            upk2(acc[rr][1], a, b); s1[rr] = (a + b) * 0.0625f;
            float tm = fmaxf(s0[rr], s1[rr]);
            #pragma unroll
            for (int off = 16; off > 0; off >>= 1)
                tm = fmaxf(tm, __shfl_xor_sync(0xffffffffu, tm, off));
            tmax[rr] = tm;
            if (tm >= m[rr] - 35.0f) active = true;
        }

        if (active) {
            #pragma unroll
            for (int rr = 0; rr < 8; rr++) {
                float nm  = fmaxf(m[rr], tmax[rr]);
                float fac = __expf(m[rr] - nm);
                float p0  = __expf(s0[rr] - nm);
                float p1  = __expf(s1[rr] - nm);
                float ps  = p0 + p1;
                #pragma unroll
                for (int off = 16; off > 0; off >>= 1)
                    ps += __shfl_xor_sync(0xffffffffu, ps, off);
                l[rr] = l[rr] * fac + ps;
                m[rr] = nm;
                Ps[(w * 8 + rr) * 64 + c]      = p0;
                Ps[(w * 8 + rr) * 64 + c + 32] = p1;
                ull f2 = pk2(fac, fac);
                #pragma unroll
                for (int j = 0; j < 4; j++) o[rr][j] = fmul2(o[rr][j], f2);
            }
            __syncwarp();

            // PV: o[rr][dims 8c..8c+7] += sum_j P[rr][j] * V[j][dims]
            #pragma unroll 2
            for (int j = 0; j < 64; j++) {
                ulonglong2 V0 = *(const ulonglong2*)&Vs[j * 256 + c * 4];        // dims 8c..8c+3
                ulonglong2 V1 = *(const ulonglong2*)&Vs[j * 256 + 128 + c * 4];  // dims 8c+4..8c+7
                #pragma unroll
                for (int rr = 0; rr < 8; rr++) {
                    float p = Ps[(w * 8 + rr) * 64 + j];
                    ull pp = pk2(p, p);
                    o[rr][0] = ffma2(pp, V0.x, o[rr][0]);
                    o[rr][1] = ffma2(pp, V0.y, o[rr][1]);
                    o[rr][2] = ffma2(pp, V1.x, o[rr][2]);
                    o[rr][3] = ffma2(pp, V1.y, o[rr][3]);
                }
            }
            __syncwarp();
        }
    }

    // epilogue: normalize and store
    #pragma unroll
    for (int rr = 0; rr < 8; rr++) {
        float inv = 1.0f / l[rr];
        float v[8];
        upk2(o[rr][0], v[0], v[1]);
        upk2(o[rr][1], v[2], v[3]);
        upk2(o[rr][2], v[4], v[5]);
        upk2(o[rr][3], v[6], v[7]);
        float* dst = &g_o[base + (size_t)(qt * 64 + w * 8 + rr) * DIM + c * 8];
        float4 a = make_float4(v[0] * inv, v[1] * inv, v[2] * inv, v[3] * inv);
        float4 b = make_float4(v[4] * inv, v[5] * inv, v[6] * inv, v[7] * inv);
        *(float4*)&dst[0] = a;
        *(float4*)&dst[4] = b;
    }
}

// ---------------------------------------------------------------------------
// Kernel 3: out[r,n] = sum_{h,d} o[h,r,d] * Cw[h*256+d, n] + Cb[n]
// block = 8 rows (warp per row), Cw staged in smem (64 KB).
// ---------------------------------------------------------------------------
__global__ __launch_bounds__(256) void final_kernel(
    const float* __restrict__ Cw, const float* __restrict__ Cb,
    float* __restrict__ out)
{
    extern __shared__ float cws[];   // 2048*8 floats
    const int tid = threadIdx.x;
    for (int i = tid; i < 4096; i += 256)
        ((float4*)cws)[i] = ((const float4*)Cw)[i];
    __syncthreads();

    const int w = tid >> 5, c = tid & 31;
    const int r = blockIdx.x * 8 + w;

    float acc[8] = {};
    #pragma unroll
    for (int h = 0; h < NHEAD; h++) {
        const float* orow = &g_o[((size_t)h * NROWS + r) * DIM];
        #pragma unroll
        for (int i = 0; i < 8; i++) {
            int d = c + i * 32;
            float ov = orow[d];
            const float* cwr = &cws[(h * DIM + d) * 8];
            #pragma unroll
            for (int n = 0; n < 8; n++)
                acc[n] = fmaf(ov, cwr[n], acc[n]);
        }
    }
    #pragma unroll
    for (int n = 0; n < 8; n++) {
        #pragma unroll
        for (int off = 16; off > 0; off >>= 1)
            acc[n] += __shfl_xor_sync(0xffffffffu, acc[n], off);
    }
    if (c == 0) {
        #pragma unroll
        for (int n = 0; n < 8; n++)
            out[r * 8 + n] = acc[n] + Cb[n];
    }
}

// ---------------------------------------------------------------------------
extern "C" void kernel_launch(void* const* d_in, const int* in_sizes, int n_in,
                              void* d_out, int out_size)
{
    const float* x    = (const float*)d_in[0];
    const float* lstm = (const float*)d_in[1];
    const float* Qw   = (const float*)d_in[2];
    const float* Qb   = (const float*)d_in[3];
    const float* Kw   = (const float*)d_in[4];
    const float* Kb   = (const float*)d_in[5];
    const float* Vw   = (const float*)d_in[6];
    const float* Vb   = (const float*)d_in[7];
    const float* Cw   = (const float*)d_in[8];
    const float* Cb   = (const float*)d_in[9];
    float* out = (float*)d_out;

    cudaFuncSetAttribute(flash_kernel, cudaFuncAttributeMaxDynamicSharedMemorySize, FLASH_SMEM);
    cudaFuncSetAttribute(final_kernel, cudaFuncAttributeMaxDynamicSharedMemorySize, 65536);

    proj_kernel<<<dim3(4, 256, 24), dim3(16, 16)>>>(x, lstm, Qw, Qb, Kw, Kb, Vw, Vb);
    flash_kernel<<<dim3(32, 64), 256, FLASH_SMEM>>>();
    final_kernel<<<2048, 256, 65536>>>(Cw, Cb, out);
}

// round 8
// speedup vs baseline: 1.7446x; 1.4542x over previous
#include <cuda_runtime.h>

#define SEQ    2048
#define DIM    256
#define NHEAD  8
#define NBATCH 8
#define NROWS  (NBATCH*SEQ)     // 16384
#define HBTOT  (NHEAD*NBATCH)   // 64

typedef unsigned long long ull;

// scratch: q,k,v,o  each [H*B][S][D] fp32 = 128 MB
__device__ float g_q[(size_t)HBTOT*SEQ*DIM];
__device__ float g_k[(size_t)HBTOT*SEQ*DIM];
__device__ float g_v[(size_t)HBTOT*SEQ*DIM];
__device__ float g_o[(size_t)HBTOT*SEQ*DIM];

// ---------------------------------------------------------------------------
// packed f32x2 helpers (FFMA2 path: only reachable via PTX fma.rn.f32x2)
// ---------------------------------------------------------------------------
__device__ __forceinline__ ull pk2(float lo, float hi) {
    ull r; asm("mov.b64 %0, {%1,%2};" : "=l"(r) : "f"(lo), "f"(hi)); return r;
}
__device__ __forceinline__ void upk2(ull v, float& lo, float& hi) {
    asm("mov.b64 {%0,%1}, %2;" : "=f"(lo), "=f"(hi) : "l"(v));
}
__device__ __forceinline__ ull ffma2(ull a, ull b, ull c) {
    ull d; asm("fma.rn.f32x2 %0, %1, %2, %3;" : "=l"(d) : "l"(a), "l"(b), "l"(c));
    return d;
}
__device__ __forceinline__ ull fmul2(ull a, ull b) {
    ull d; asm("mul.rn.f32x2 %0, %1, %2;" : "=l"(d) : "l"(a), "l"(b));
    return d;
}
__device__ __forceinline__ void cpa16(float* dst, const float* src) {
    unsigned s = (unsigned)__cvta_generic_to_shared(dst);
    asm volatile("cp.async.cg.shared.global [%0], [%1], 16;" :: "r"(s), "l"(src));
}

// ---------------------------------------------------------------------------
// Kernel 1: QKV projections.  out[h,r,d] = sum_f A[r,f]*W[h,f,d] + b[h,d]
// grid: (4 n-tiles, 256 m-tiles, 24 matrices), block 16x16, 64x64x16 tiling.
// ---------------------------------------------------------------------------
__global__ __launch_bounds__(256) void proj_kernel(
    const float* __restrict__ x, const float* __restrict__ lstm,
    const float* __restrict__ Qw, const float* __restrict__ Qb,
    const float* __restrict__ Kw, const float* __restrict__ Kb,
    const float* __restrict__ Vw, const float* __restrict__ Vb)
{
    __shared__ float As[16][64];
    __shared__ float Bs[16][64];

    const int bz = blockIdx.z;
    const int type = bz >> 3, h = bz & 7;
    const float* A; const float* W; const float* bias; float* out;
    if (type == 0)      { A = lstm; W = Qw; bias = Qb; out = g_q; }
    else if (type == 1) { A = x;    W = Kw; bias = Kb; out = g_k; }
    else                { A = x;    W = Vw; bias = Vb; out = g_v; }
    W    += h * DIM * DIM;
    bias += h * DIM;
    out  += (size_t)h * NROWS * DIM;

    const int r0 = blockIdx.y * 64, d0 = blockIdx.x * 64;
    const int tx = threadIdx.x, ty = threadIdx.y;
    const int tid = ty * 16 + tx;

    const int arow = tid >> 2,  ak4 = (tid & 3)  * 4;
    const int brow = tid >> 4,  bc4 = (tid & 15) * 4;

    ull acc[4][2];
    #pragma unroll
    for (int i = 0; i < 4; i++) { acc[i][0] = 0ull; acc[i][1] = 0ull; }

    for (int kt = 0; kt < DIM; kt += 16) {
        float4 a = *(const float4*)&A[(size_t)(r0 + arow) * DIM + kt + ak4];
        float4 b = *(const float4*)&W[(size_t)(kt + brow) * DIM + d0 + bc4];
        __syncthreads();   // previous iteration's compute done
        As[ak4 + 0][arow] = a.x;
        As[ak4 + 1][arow] = a.y;
        As[ak4 + 2][arow] = a.z;
        As[ak4 + 3][arow] = a.w;
        *(float4*)&Bs[brow][bc4] = b;
        __syncthreads();
        #pragma unroll
        for (int kk = 0; kk < 16; kk++) {
            float4 av = *(const float4*)&As[kk][ty * 4];
            ulonglong2 bv = *(const ulonglong2*)&Bs[kk][tx * 4];
            ull a0 = pk2(av.x, av.x), a1 = pk2(av.y, av.y);
            ull a2 = pk2(av.z, av.z), a3 = pk2(av.w, av.w);
            acc[0][0] = ffma2(a0, bv.x, acc[0][0]);
            acc[0][1] = ffma2(a0, bv.y, acc[0][1]);
            acc[1][0] = ffma2(a1, bv.x, acc[1][0]);
            acc[1][1] = ffma2(a1, bv.y, acc[1][1]);
            acc[2][0] = ffma2(a2, bv.x, acc[2][0]);
            acc[2][1] = ffma2(a2, bv.y, acc[2][1]);
            acc[3][0] = ffma2(a3, bv.x, acc[3][0]);
            acc[3][1] = ffma2(a3, bv.y, acc[3][1]);
        }
    }

    #pragma unroll
    for (int i = 0; i < 4; i++) {
        float4 o;
        upk2(acc[i][0], o.x, o.y);
        upk2(acc[i][1], o.z, o.w);
        o.x += bias[d0 + tx * 4 + 0];
        o.y += bias[d0 + tx * 4 + 1];
        o.z += bias[d0 + tx * 4 + 2];
        o.w += bias[d0 + tx * 4 + 3];
        *(float4*)&out[(size_t)(r0 + ty * 4 + i) * DIM + d0 + tx * 4] = o;
    }
}

// ---------------------------------------------------------------------------
// Kernel 2: flash attention with SPARSE softmax/PV.
// grid (32 q-tiles, 64 hb), 256 threads.  Warp w owns q rows w*8..w*8+7;
// lane c owns score columns c and c+32 of a 64-wide K tile.
// Dense work = QK only (FFMA2).  Per row: tile max; if within 35 of running
// max, ballot candidate lanes (s >= m-35) and ONLY those get exp + gathered
// o += p * V[j] straight from global (warp-coalesced 1KB row reads).
// Everything below m-35 contributes < 6e-16 relatively -> dropped exactly as
// the previous version's tile-skip did.
// K tiles double-buffered in smem via cp.async (Q 64KB + 2x64KB K = 192KB).
// ---------------------------------------------------------------------------
#define FLASH_SMEM (3*64*256*4)   // 196608 bytes

__global__ __launch_bounds__(256, 1) void flash_kernel()
{
    extern __shared__ float sm[];
    float* Qs = sm;               // [64][256] linear
    float* K0 = sm + 64 * 256;    // two [64][256] xor-swizzled buffers

    const int qt = blockIdx.x;    // 0..31
    const int hb = blockIdx.y;    // 0..63
    const size_t base = (size_t)hb * SEQ * DIM;
    const int tid = threadIdx.x;
    const int w = tid >> 5, c = tid & 31;
    const int cx = c & 7;

    // prefetch K tile 0 (async), then load Q tile 64x256
    #pragma unroll
    for (int i = 0; i < 16; i++) {
        int u = tid + i * 256;
        int r = u >> 6, k4 = u & 63;
        cpa16(&K0[r * 256 + ((k4 ^ (r & 7)) << 2)],
              &g_k[base + (size_t)r * DIM + k4 * 4]);
    }
    asm volatile("cp.async.commit_group;");

    #pragma unroll
    for (int i = 0; i < 16; i++) {
        int u = tid + i * 256;
        int r = u >> 6, k4 = u & 63;
        *(float4*)&Qs[r * 256 + k4 * 4] =
            *(const float4*)&g_q[base + (size_t)(qt * 64 + r) * DIM + k4 * 4];
    }

    ull o[8][4];                  // packed pairs covering dims 8c..8c+7
    #pragma unroll
    for (int i = 0; i < 8; i++)
        #pragma unroll
        for (int j = 0; j < 4; j++) o[i][j] = 0ull;
    float m[8], l[8];
    #pragma unroll
    for (int i = 0; i < 8; i++) { m[i] = -3.0e38f; l[i] = 0.f; }

    int buf = 0;
    for (int kt = 0; kt < SEQ / 64; kt++) {
        asm volatile("cp.async.wait_group 0;");
        __syncthreads();          // current K buffer visible; prev reads done

        if (kt + 1 < SEQ / 64) {  // prefetch next tile into other buffer
            float* Kn = K0 + (buf ^ 1) * 64 * 256;
            #pragma unroll
            for (int i = 0; i < 16; i++) {
                int u = tid + i * 256;
                int r = u >> 6, k4 = u & 63;
                cpa16(&Kn[r * 256 + ((k4 ^ (r & 7)) << 2)],
                      &g_k[base + (size_t)((kt + 1) * 64 + r) * DIM + k4 * 4]);
            }
            asm volatile("cp.async.commit_group;");
        }

        const float* Kc = K0 + buf * 64 * 256;

        // dense QK: lane computes s[rr][col c] and s[rr][col c+32]
        ull acc[8][2];
        #pragma unroll
        for (int rr = 0; rr < 8; rr++) { acc[rr][0] = 0ull; acc[rr][1] = 0ull; }

        const float* k0p = &Kc[c * 256];
        const float* k1p = &Kc[(c + 32) * 256];   // same xor phase: (c+32)&7==c&7
        #pragma unroll 4
        for (int k4 = 0; k4 < 64; k4++) {
            int sc = (k4 ^ cx) << 2;
            ulonglong2 kv0 = *(const ulonglong2*)&k0p[sc];
            ulonglong2 kv1 = *(const ulonglong2*)&k1p[sc];
            #pragma unroll
            for (int rr = 0; rr < 8; rr++) {
                ulonglong2 qv = *(const ulonglong2*)&Qs[(w * 8 + rr) * 256 + k4 * 4];
                acc[rr][0] = ffma2(qv.x, kv0.x, acc[rr][0]);
                acc[rr][0] = ffma2(qv.y, kv0.y, acc[rr][0]);
                acc[rr][1] = ffma2(qv.x, kv1.x, acc[rr][1]);
                acc[rr][1] = ffma2(qv.y, kv1.y, acc[rr][1]);
            }
        }

        // sparse softmax + PV gather, per row
        const float* vtile = &g_v[base + (size_t)(kt * 64) * DIM + c * 8];
        #pragma unroll
        for (int rr = 0; rr < 8; rr++) {
            float a, b;
            upk2(acc[rr][0], a, b); float s0 = (a + b) * 0.0625f;
            upk2(acc[rr][1], a, b); float s1 = (a + b) * 0.0625f;
            float tm = fmaxf(s0, s1);
            #pragma unroll
            for (int off = 16; off > 0; off >>= 1)
                tm = fmaxf(tm, __shfl_xor_sync(0xffffffffu, tm, off));

            if (tm >= m[rr] - 35.0f) {            // warp-uniform
                float nm = fmaxf(m[rr], tm);
                if (nm > m[rr]) {                 // rescale only on max update
                    float fac = __expf(m[rr] - nm);
                    l[rr] *= fac;
                    ull f2 = pk2(fac, fac);
                    o[rr][0] = fmul2(o[rr][0], f2);
                    o[rr][1] = fmul2(o[rr][1], f2);
                    o[rr][2] = fmul2(o[rr][2], f2);
                    o[rr][3] = fmul2(o[rr][3], f2);
                    m[rr] = nm;
                }
                float thr = nm - 35.0f;
                unsigned b0 = __ballot_sync(0xffffffffu, s0 >= thr);
                unsigned b1 = __ballot_sync(0xffffffffu, s1 >= thr);
                while (b0) {
                    int ln = __ffs(b0) - 1; b0 &= b0 - 1;
                    float sv = __shfl_sync(0xffffffffu, s0, ln);
                    float p = __expf(sv - nm);
                    l[rr] += p;
                    const ulonglong2* vr =
                        (const ulonglong2*)(vtile + (size_t)ln * DIM);
                    ulonglong2 V0 = vr[0], V1 = vr[1];
                    ull pp = pk2(p, p);
                    o[rr][0] = ffma2(pp, V0.x, o[rr][0]);
                    o[rr][1] = ffma2(pp, V0.y, o[rr][1]);
                    o[rr][2] = ffma2(pp, V1.x, o[rr][2]);
                    o[rr][3] = ffma2(pp, V1.y, o[rr][3]);
                }
                while (b1) {
                    int ln = __ffs(b1) - 1; b1 &= b1 - 1;
                    float sv = __shfl_sync(0xffffffffu, s1, ln);
                    float p = __expf(sv - nm);
                    l[rr] += p;
                    const ulonglong2* vr =
                        (const ulonglong2*)(vtile + (size_t)(ln + 32) * DIM);
                    ulonglong2 V0 = vr[0], V1 = vr[1];
                    ull pp = pk2(p, p);
                    o[rr][0] = ffma2(pp, V0.x, o[rr][0]);
                    o[rr][1] = ffma2(pp, V0.y, o[rr][1]);
                    o[rr][2] = ffma2(pp, V1.x, o[rr][2]);
                    o[rr][3] = ffma2(pp, V1.y, o[rr][3]);
                }
            }
        }
        buf ^= 1;
    }

    // epilogue: normalize and store
    #pragma unroll
    for (int rr = 0; rr < 8; rr++) {
        float inv = 1.0f / l[rr];
        float v[8];
        upk2(o[rr][0], v[0], v[1]);
        upk2(o[rr][1], v[2], v[3]);
        upk2(o[rr][2], v[4], v[5]);
        upk2(o[rr][3], v[6], v[7]);
        float* dst = &g_o[base + (size_t)(qt * 64 + w * 8 + rr) * DIM + c * 8];
        float4 x = make_float4(v[0] * inv, v[1] * inv, v[2] * inv, v[3] * inv);
        float4 y = make_float4(v[4] * inv, v[5] * inv, v[6] * inv, v[7] * inv);
        *(float4*)&dst[0] = x;
        *(float4*)&dst[4] = y;
    }
}

// ---------------------------------------------------------------------------
// Kernel 3: out[r,n] = sum_{h,d} o[h,r,d] * Cw[h*256+d, n] + Cb[n]
// block = 8 rows (warp per row), Cw staged in smem (64 KB).
// ---------------------------------------------------------------------------
__global__ __launch_bounds__(256) void final_kernel(
    const float* __restrict__ Cw, const float* __restrict__ Cb,
    float* __restrict__ out)
{
    extern __shared__ float cws[];   // 2048*8 floats
    const int tid = threadIdx.x;
    for (int i = tid; i < 4096; i += 256)
        ((float4*)cws)[i] = ((const float4*)Cw)[i];
    __syncthreads();

    const int w = tid >> 5, c = tid & 31;
    const int r = blockIdx.x * 8 + w;

    float acc[8] = {};
    #pragma unroll
    for (int h = 0; h < NHEAD; h++) {
        const float* orow = &g_o[((size_t)h * NROWS + r) * DIM];
        #pragma unroll
        for (int i = 0; i < 8; i++) {
            int d = c + i * 32;
            float ov = orow[d];
            const float* cwr = &cws[(h * DIM + d) * 8];
            #pragma unroll
            for (int n = 0; n < 8; n++)
                acc[n] = fmaf(ov, cwr[n], acc[n]);
        }
    }
    #pragma unroll
    for (int n = 0; n < 8; n++) {
        #pragma unroll
        for (int off = 16; off > 0; off >>= 1)
            acc[n] += __shfl_xor_sync(0xffffffffu, acc[n], off);
    }
    if (c == 0) {
        #pragma unroll
        for (int n = 0; n < 8; n++)
            out[r * 8 + n] = acc[n] + Cb[n];
    }
}

// ---------------------------------------------------------------------------
extern "C" void kernel_launch(void* const* d_in, const int* in_sizes, int n_in,
                              void* d_out, int out_size)
{
    const float* x    = (const float*)d_in[0];
    const float* lstm = (const float*)d_in[1];
    const float* Qw   = (const float*)d_in[2];
    const float* Qb   = (const float*)d_in[3];
    const float* Kw   = (const float*)d_in[4];
    const float* Kb   = (const float*)d_in[5];
    const float* Vw   = (const float*)d_in[6];
    const float* Vb   = (const float*)d_in[7];
    const float* Cw   = (const float*)d_in[8];
    const float* Cb   = (const float*)d_in[9];
    float* out = (float*)d_out;

    cudaFuncSetAttribute(flash_kernel, cudaFuncAttributeMaxDynamicSharedMemorySize, FLASH_SMEM);
    cudaFuncSetAttribute(final_kernel, cudaFuncAttributeMaxDynamicSharedMemorySize, 65536);

    proj_kernel<<<dim3(4, 256, 24), dim3(16, 16)>>>(x, lstm, Qw, Qb, Kw, Kb, Vw, Vb);
    flash_kernel<<<dim3(32, 64), 256, FLASH_SMEM>>>();
    final_kernel<<<2048, 256, 65536>>>(Cw, Cb, out);
}

// round 9
// speedup vs baseline: 1.8816x; 1.0786x over previous
#include <cuda_runtime.h>

#define SEQ    2048
#define DIM    256
#define NHEAD  8
#define NBATCH 8
#define NROWS  (NBATCH*SEQ)     // 16384
#define HBTOT  (NHEAD*NBATCH)   // 64

typedef unsigned long long ull;

// scratch: q,k,v  each [H*B][S][D] fp32 = 128 MB
__device__ float g_q[(size_t)HBTOT*SEQ*DIM];
__device__ float g_k[(size_t)HBTOT*SEQ*DIM];
__device__ float g_v[(size_t)HBTOT*SEQ*DIM];

// ---------------------------------------------------------------------------
// packed f32x2 helpers (FFMA2 path: only reachable via PTX fma.rn.f32x2)
// ---------------------------------------------------------------------------
__device__ __forceinline__ ull pk2(float lo, float hi) {
    ull r; asm("mov.b64 %0, {%1,%2};" : "=l"(r) : "f"(lo), "f"(hi)); return r;
}
__device__ __forceinline__ void upk2(ull v, float& lo, float& hi) {
    asm("mov.b64 {%0,%1}, %2;" : "=f"(lo), "=f"(hi) : "l"(v));
}
__device__ __forceinline__ ull ffma2(ull a, ull b, ull c) {
    ull d; asm("fma.rn.f32x2 %0, %1, %2, %3;" : "=l"(d) : "l"(a), "l"(b), "l"(c));
    return d;
}
__device__ __forceinline__ ull fmul2(ull a, ull b) {
    ull d; asm("mul.rn.f32x2 %0, %1, %2;" : "=l"(d) : "l"(a), "l"(b));
    return d;
}
__device__ __forceinline__ void cpa16(float* dst, const float* src) {
    unsigned s = (unsigned)__cvta_generic_to_shared(dst);
    asm volatile("cp.async.cg.shared.global [%0], [%1], 16;" :: "r"(s), "l"(src));
}

// ---------------------------------------------------------------------------
// Kernel 0: init output with bias (flash accumulates into it atomically)
// ---------------------------------------------------------------------------
__global__ __launch_bounds__(256) void init_out_kernel(
    const float* __restrict__ Cb, float* __restrict__ out)
{
    int idx = blockIdx.x * 256 + threadIdx.x;     // 0..131071
    out[idx] = Cb[idx & 7];
}

// ---------------------------------------------------------------------------
// Kernel 1: QKV projections.  out[h,r,d] = sum_f A[r,f]*W[h,f,d] + b[h,d]
// grid: (4 n-tiles, 256 m-tiles, 24 matrices), block 16x16, 64x64 tile.
// K-chunks of 32, cp.async double-buffered (loads overlap compute).
// ---------------------------------------------------------------------------
__global__ __launch_bounds__(256) void proj_kernel(
    const float* __restrict__ x, const float* __restrict__ lstm,
    const float* __restrict__ Qw, const float* __restrict__ Qb,
    const float* __restrict__ Kw, const float* __restrict__ Kb,
    const float* __restrict__ Vw, const float* __restrict__ Vb)
{
    __shared__ float As[2][64][32];   // [buf][row][k]
    __shared__ float Bs[2][32][64];   // [buf][k][col]

    const int bz = blockIdx.z;
    const int type = bz >> 3, h = bz & 7;
    const float* A; const float* W; const float* bias; float* out;
    if (type == 0)      { A = lstm; W = Qw; bias = Qb; out = g_q; }
    else if (type == 1) { A = x;    W = Kw; bias = Kb; out = g_k; }
    else                { A = x;    W = Vw; bias = Vb; out = g_v; }
    W    += h * DIM * DIM;
    bias += h * DIM;
    out  += (size_t)h * NROWS * DIM;

    const int r0 = blockIdx.y * 64, d0 = blockIdx.x * 64;
    const int tx = threadIdx.x, ty = threadIdx.y;
    const int tid = ty * 16 + tx;

    // cp.async load of one 64x32 A chunk + 32x64 B chunk into buffer `buf`
    auto load_chunk = [&](int buf, int kt) {
        #pragma unroll
        for (int i = 0; i < 2; i++) {
            int u = tid + i * 256;                // 0..511
            int ar = u >> 3, as = (u & 7) * 4;    // A: row, 4-float seg
            cpa16(&As[buf][ar][as],
                  &A[(size_t)(r0 + ar) * DIM + kt + as]);
            int br = u >> 4, bs = (u & 15) * 4;   // B: k-row, 4-float seg
            cpa16(&Bs[buf][br][bs],
                  &W[(size_t)(kt + br) * DIM + d0 + bs]);
        }
    };

    ull acc[4][2];
    #pragma unroll
    for (int i = 0; i < 4; i++) { acc[i][0] = 0ull; acc[i][1] = 0ull; }

    load_chunk(0, 0);
    asm volatile("cp.async.commit_group;");

    int buf = 0;
    for (int ck = 0; ck < 8; ck++) {
        if (ck + 1 < 8) {
            load_chunk(buf ^ 1, (ck + 1) * 32);
            asm volatile("cp.async.commit_group;");
            asm volatile("cp.async.wait_group 1;");
        } else {
            asm volatile("cp.async.wait_group 0;");
        }
        __syncthreads();

        #pragma unroll
        for (int kk = 0; kk < 32; kk++) {
            float a0 = As[buf][ty * 4 + 0][kk];
            float a1 = As[buf][ty * 4 + 1][kk];
            float a2 = As[buf][ty * 4 + 2][kk];
            float a3 = As[buf][ty * 4 + 3][kk];
            ulonglong2 bv = *(const ulonglong2*)&Bs[buf][kk][tx * 4];
            ull p0 = pk2(a0, a0), p1 = pk2(a1, a1);
            ull p2 = pk2(a2, a2), p3 = pk2(a3, a3);
            acc[0][0] = ffma2(p0, bv.x, acc[0][0]);
            acc[0][1] = ffma2(p0, bv.y, acc[0][1]);
            acc[1][0] = ffma2(p1, bv.x, acc[1][0]);
            acc[1][1] = ffma2(p1, bv.y, acc[1][1]);
            acc[2][0] = ffma2(p2, bv.x, acc[2][0]);
            acc[2][1] = ffma2(p2, bv.y, acc[2][1]);
            acc[3][0] = ffma2(p3, bv.x, acc[3][0]);
            acc[3][1] = ffma2(p3, bv.y, acc[3][1]);
        }
        __syncthreads();   // compute done before buf is overwritten next iter
        buf ^= 1;
    }

    #pragma unroll
    for (int i = 0; i < 4; i++) {
        float4 o;
        upk2(acc[i][0], o.x, o.y);
        upk2(acc[i][1], o.z, o.w);
        o.x += bias[d0 + tx * 4 + 0];
        o.y += bias[d0 + tx * 4 + 1];
        o.z += bias[d0 + tx * 4 + 2];
        o.w += bias[d0 + tx * 4 + 3];
        *(float4*)&out[(size_t)(r0 + ty * 4 + i) * DIM + d0 + tx * 4] = o;
    }
}

// ---------------------------------------------------------------------------
// Kernel 2: flash attention with SPARSE softmax/PV + fused final projection.
// grid (32 q-tiles, 64 hb), 256 threads.  Warp w owns q rows w*8..w*8+7;
// lane c owns score columns c and c+32 of a 64-wide K tile.
// Dense work = QK only (FFMA2).  Candidates (s >= m-35) get exp + gathered
// o += p * V[j] straight from global.  Below m-35 contributes < 6e-16.
// K tiles double-buffered in smem via cp.async (Q 64KB + 2x64KB K = 192KB).
// Epilogue: o rows are contracted with this head's Cw slice and atomically
// accumulated into out (pre-initialized with Cb) — no g_o, no final kernel.
// ---------------------------------------------------------------------------
#define FLASH_SMEM (3*64*256*4)   // 196608 bytes

__global__ __launch_bounds__(256, 1) void flash_kernel(
    const float* __restrict__ Cw, float* __restrict__ out)
{
    extern __shared__ float sm[];
    float* Qs = sm;               // [64][256] linear
    float* K0 = sm + 64 * 256;    // two [64][256] xor-swizzled buffers

    const int qt = blockIdx.x;    // 0..31
    const int hb = blockIdx.y;    // 0..63
    const size_t base = (size_t)hb * SEQ * DIM;
    const int tid = threadIdx.x;
    const int w = tid >> 5, c = tid & 31;
    const int cx = c & 7;

    // prefetch K tile 0 (async), then load Q tile 64x256
    #pragma unroll
    for (int i = 0; i < 16; i++) {
        int u = tid + i * 256;
        int r = u >> 6, k4 = u & 63;
        cpa16(&K0[r * 256 + ((k4 ^ (r & 7)) << 2)],
              &g_k[base + (size_t)r * DIM + k4 * 4]);
    }
    asm volatile("cp.async.commit_group;");

    #pragma unroll
    for (int i = 0; i < 16; i++) {
        int u = tid + i * 256;
        int r = u >> 6, k4 = u & 63;
        *(float4*)&Qs[r * 256 + k4 * 4] =
            *(const float4*)&g_q[base + (size_t)(qt * 64 + r) * DIM + k4 * 4];
    }

    ull o[8][4];                  // packed pairs covering dims 8c..8c+7
    #pragma unroll
    for (int i = 0; i < 8; i++)
        #pragma unroll
        for (int j = 0; j < 4; j++) o[i][j] = 0ull;
    float m[8], l[8];
    #pragma unroll
    for (int i = 0; i < 8; i++) { m[i] = -3.0e38f; l[i] = 0.f; }

    int buf = 0;
    for (int kt = 0; kt < SEQ / 64; kt++) {
        asm volatile("cp.async.wait_group 0;");
        __syncthreads();          // current K buffer visible; prev reads done

        if (kt + 1 < SEQ / 64) {  // prefetch next tile into other buffer
            float* Kn = K0 + (buf ^ 1) * 64 * 256;
            #pragma unroll
            for (int i = 0; i < 16; i++) {
                int u = tid + i * 256;
                int r = u >> 6, k4 = u & 63;
                cpa16(&Kn[r * 256 + ((k4 ^ (r & 7)) << 2)],
                      &g_k[base + (size_t)((kt + 1) * 64 + r) * DIM + k4 * 4]);
            }
            asm volatile("cp.async.commit_group;");
        }

        const float* Kc = K0 + buf * 64 * 256;

        // dense QK: lane computes s[rr][col c] and s[rr][col c+32]
        ull acc[8][2];
        #pragma unroll
        for (int rr = 0; rr < 8; rr++) { acc[rr][0] = 0ull; acc[rr][1] = 0ull; }

        const float* k0p = &Kc[c * 256];
        const float* k1p = &Kc[(c + 32) * 256];   // same xor phase: (c+32)&7==c&7
        #pragma unroll 4
        for (int k4 = 0; k4 < 64; k4++) {
            int sc = (k4 ^ cx) << 2;
            ulonglong2 kv0 = *(const ulonglong2*)&k0p[sc];
            ulonglong2 kv1 = *(const ulonglong2*)&k1p[sc];
            #pragma unroll
            for (int rr = 0; rr < 8; rr++) {
                ulonglong2 qv = *(const ulonglong2*)&Qs[(w * 8 + rr) * 256 + k4 * 4];
                acc[rr][0] = ffma2(qv.x, kv0.x, acc[rr][0]);
                acc[rr][0] = ffma2(qv.y, kv0.y, acc[rr][0]);
                acc[rr][1] = ffma2(qv.x, kv1.x, acc[rr][1]);
                acc[rr][1] = ffma2(qv.y, kv1.y, acc[rr][1]);
            }
        }

        // sparse softmax + PV gather, per row
        const float* vtile = &g_v[base + (size_t)(kt * 64) * DIM + c * 8];
        #pragma unroll
        for (int rr = 0; rr < 8; rr++) {
            float a, b;
            upk2(acc[rr][0], a, b); float s0 = (a + b) * 0.0625f;
            upk2(acc[rr][1], a, b); float s1 = (a + b) * 0.0625f;
            float tm = fmaxf(s0, s1);
            #pragma unroll
            for (int off = 16; off > 0; off >>= 1)
                tm = fmaxf(tm, __shfl_xor_sync(0xffffffffu, tm, off));

            if (tm >= m[rr] - 35.0f) {            // warp-uniform
                float nm = fmaxf(m[rr], tm);
                if (nm > m[rr]) {                 // rescale only on max update
                    float fac = __expf(m[rr] - nm);
                    l[rr] *= fac;
                    ull f2 = pk2(fac, fac);
                    o[rr][0] = fmul2(o[rr][0], f2);
                    o[rr][1] = fmul2(o[rr][1], f2);
                    o[rr][2] = fmul2(o[rr][2], f2);
                    o[rr][3] = fmul2(o[rr][3], f2);
                    m[rr] = nm;
                }
                float thr = nm - 35.0f;
                unsigned b0 = __ballot_sync(0xffffffffu, s0 >= thr);
                unsigned b1 = __ballot_sync(0xffffffffu, s1 >= thr);
                while (b0) {
                    int ln = __ffs(b0) - 1; b0 &= b0 - 1;
                    float sv = __shfl_sync(0xffffffffu, s0, ln);
                    float p = __expf(sv - nm);
                    l[rr] += p;
                    const ulonglong2* vr =
                        (const ulonglong2*)(vtile + (size_t)ln * DIM);
                    ulonglong2 V0 = vr[0], V1 = vr[1];
                    ull pp = pk2(p, p);
                    o[rr][0] = ffma2(pp, V0.x, o[rr][0]);
                    o[rr][1] = ffma2(pp, V0.y, o[rr][1]);
                    o[rr][2] = ffma2(pp, V1.x, o[rr][2]);
                    o[rr][3] = ffma2(pp, V1.y, o[rr][3]);
                }
                while (b1) {
                    int ln = __ffs(b1) - 1; b1 &= b1 - 1;
                    float sv = __shfl_sync(0xffffffffu, s1, ln);
                    float p = __expf(sv - nm);
                    l[rr] += p;
                    const ulonglong2* vr =
                        (const ulonglong2*)(vtile + (size_t)(ln + 32) * DIM);
                    ulonglong2 V0 = vr[0], V1 = vr[1];
                    ull pp = pk2(p, p);
                    o[rr][0] = ffma2(pp, V0.x, o[rr][0]);
                    o[rr][1] = ffma2(pp, V0.y, o[rr][1]);
                    o[rr][2] = ffma2(pp, V1.x, o[rr][2]);
                    o[rr][3] = ffma2(pp, V1.y, o[rr][3]);
                }
            }
        }
        buf ^= 1;
    }

    // ------------------------------------------------------------------
    // fused epilogue: out[r,n] += sum_d o_norm[r,d] * Cw[h*256+d, n]
    // lane c owns dims 8c..8c+7; butterfly-reduce 8 n-sums across lanes.
    // ------------------------------------------------------------------
    const int h = hb >> 3;
    const int out_r0 = (hb & 7) * SEQ + qt * 64 + w * 8;

    float cw[8][8];               // [i dim-in-slice][n]
    const float* cwp = Cw + ((size_t)h * 256 + c * 8) * 8;
    #pragma unroll
    for (int i = 0; i < 8; i++) {
        float4 u0 = *(const float4*)&cwp[i * 8 + 0];
        float4 u1 = *(const float4*)&cwp[i * 8 + 4];
        cw[i][0] = u0.x; cw[i][1] = u0.y; cw[i][2] = u0.z; cw[i][3] = u0.w;
        cw[i][4] = u1.x; cw[i][5] = u1.y; cw[i][6] = u1.z; cw[i][7] = u1.w;
    }

    #pragma unroll
    for (int rr = 0; rr < 8; rr++) {
        float inv = 1.0f / l[rr];
        float v[8];
        upk2(o[rr][0], v[0], v[1]);
        upk2(o[rr][1], v[2], v[3]);
        upk2(o[rr][2], v[4], v[5]);
        upk2(o[rr][3], v[6], v[7]);
        float pn[8] = {};
        #pragma unroll
        for (int i = 0; i < 8; i++) {
            float ov = v[i] * inv;
            #pragma unroll
            for (int n = 0; n < 8; n++)
                pn[n] = fmaf(ov, cw[i][n], pn[n]);
        }
        #pragma unroll
        for (int n = 0; n < 8; n++) {
            #pragma unroll
            for (int off = 16; off > 0; off >>= 1)
                pn[n] += __shfl_xor_sync(0xffffffffu, pn[n], off);
        }
        if (c < 8)
            atomicAdd(&out[(size_t)(out_r0 + rr) * 8 + c], pn[c]);
    }
}

// ---------------------------------------------------------------------------
extern "C" void kernel_launch(void* const* d_in, const int* in_sizes, int n_in,
                              void* d_out, int out_size)
{
    const float* x    = (const float*)d_in[0];
    const float* lstm = (const float*)d_in[1];
    const float* Qw   = (const float*)d_in[2];
    const float* Qb   = (const float*)d_in[3];
    const float* Kw   = (const float*)d_in[4];
    const float* Kb   = (const float*)d_in[5];
    const float* Vw   = (const float*)d_in[6];
    const float* Vb   = (const float*)d_in[7];
    const float* Cw   = (const float*)d_in[8];
    const float* Cb   = (const float*)d_in[9];
    float* out = (float*)d_out;

    cudaFuncSetAttribute(flash_kernel, cudaFuncAttributeMaxDynamicSharedMemorySize, FLASH_SMEM);

    init_out_kernel<<<512, 256>>>(Cb, out);     // out[r,n] = Cb[n]
    proj_kernel<<<dim3(4, 256, 24), dim3(16, 16)>>>(x, lstm, Qw, Qb, Kw, Kb, Vw, Vb);
    flash_kernel<<<dim3(32, 64), 256, FLASH_SMEM>>>(Cw, out);
}